// round 14
// baseline (speedup 1.0000x reference)
#include <cuda_runtime.h>
#include <math.h>
#include <stdint.h>

#define BB 16384

__device__ __align__(16) float g_Wcat[128 * 1280];
__device__ __align__(16) float g_PR[(size_t)BB * 1280];
__device__ __align__(16) float g_U[(size_t)BB * 1024];
__device__ __align__(16) float g_Z1[(size_t)BB * 256];
__device__ __align__(16) float g_H1[(size_t)BB * 256];

__device__ __forceinline__ float wsum(float v) {
#pragma unroll
  for (int o = 16; o; o >>= 1) v += __shfl_xor_sync(0xffffffffu, v, o);
  return v;
}
__device__ __forceinline__ float wmax(float v) {
#pragma unroll
  for (int o = 16; o; o >>= 1) v = fmaxf(v, __shfl_xor_sync(0xffffffffu, v, o));
  return v;
}

#define FMA2(d, a, b) \
  asm("fma.rn.f32x2 %0, %1, %2, %0;" : "+l"(d) : "l"(a), "l"(b))
__device__ __forceinline__ unsigned long long dup2(float x) {
  unsigned long long r;
  asm("mov.b64 %0, {%1, %1};" : "=l"(r) : "f"(x));
  return r;
}
__device__ __forceinline__ unsigned long long pk2(float x, float y) {
  unsigned long long r;
  asm("mov.b64 %0, {%1, %2};" : "=l"(r) : "f"(x), "f"(y));
  return r;
}
__device__ __forceinline__ float2 unpk(unsigned long long p) {
  float2 r;
  asm("mov.b64 {%0, %1}, %2;" : "=f"(r.x), "=f"(r.y) : "l"(p));
  return r;
}
__device__ __forceinline__ void cpa16(uint32_t s, const void* g) {
  asm volatile("cp.async.cg.shared.global [%0], [%1], 16;" :: "r"(s), "l"(g));
}
#define CP_COMMIT() asm volatile("cp.async.commit_group;" ::: "memory")
#define CP_WAIT0() asm volatile("cp.async.wait_group 0;" ::: "memory")

__device__ __forceinline__ int SW(int d) {
  return (d & ~31) | ((d & 31) ^ (((d >> 5) & 3) << 2));
}

__device__ __forceinline__ void fast_sincos(float z, float& s, float& c) {
  float t = rintf(z * 0.63661977236758134f);
  int qi = (int)t;
  float r = fmaf(t, -1.5703125f, z);
  r = fmaf(t, -4.83751296997070312e-4f, r);
  r = fmaf(t, -7.54978995489188e-8f, r);
  float r2 = r * r;
  float sp = fmaf(r2, -1.9515296e-4f, 8.3321608e-3f);
  sp = fmaf(r2, sp, -1.6666654611e-1f);
  float sinr = fmaf(r * r2, sp, r);
  float cp = fmaf(r2, -1.388731625493765e-3f, 4.166664568298827e-2f);
  cp = fmaf(r2, cp, -0.5f);
  float cosr = fmaf(r2, cp, 1.0f);
  int qq = qi & 3;
  float ss = (qq & 1) ? cosr : sinr;
  float cc = (qq & 1) ? sinr : cosr;
  s = (qq & 2) ? -ss : ss;
  c = ((qq + 1) & 2) ? -cc : cc;
}

// per-warp LN helper (proven)
__device__ __forceinline__ void ln_epilogue(
    float (*v)[4], int rbase, int colslab, int cb,
    float* redS, float* redQ,
    const float* gamma, const float* beta, float* C, int ldc, size_t m0) {
  int lane = threadIdx.x & 31;
#pragma unroll
  for (int r = 0; r < 16; r++) {
    float s = v[r][0] + v[r][1] + v[r][2] + v[r][3];
    float q = v[r][0] * v[r][0] + v[r][1] * v[r][1] +
              v[r][2] * v[r][2] + v[r][3] * v[r][3];
    s = wsum(s);
    q = wsum(q);
    if (lane == 0) {
      redS[colslab * 64 + rbase + r] = s;
      redQ[colslab * 64 + rbase + r] = q;
    }
  }
  __syncthreads();
  float4 gg = *(const float4*)&gamma[cb];
  float4 ee = *(const float4*)&beta[cb];
#pragma unroll
  for (int r = 0; r < 16; r++) {
    float s = redS[rbase + r] + redS[64 + rbase + r];
    float q = redQ[rbase + r] + redQ[64 + rbase + r];
    float mean = s * (1.f / 256.f);
    float var = fmaf(-mean, mean, q * (1.f / 256.f));
    float rstd = rsqrtf(var + 1e-5f);
    float4 o;
    o.x = (v[r][0] - mean) * rstd * gg.x + ee.x;
    o.y = (v[r][1] - mean) * rstd * gg.y + ee.y;
    o.z = (v[r][2] - mean) * rstd * gg.z + ee.z;
    o.w = (v[r][3] - mean) * rstd * gg.w + ee.w;
    *(float4*)&C[(m0 + rbase + r) * ldc + cb] = o;
  }
}

// ---------------- K0 ----------------
__global__ void __launch_bounds__(256) mqk_kernel(const float* __restrict__ Wq,
                                                  const float* __restrict__ Wk) {
  __shared__ float sWq[16 * 68];
  __shared__ float sWk[128 * 68];
  int h = blockIdx.x, is = blockIdx.y, tid = threadIdx.x;
  {
    int il = tid >> 4, d4 = tid & 15;
    *(float4*)&sWq[il * 68 + d4 * 4] =
        *(const float4*)&Wq[(size_t)(is * 16 + il) * 256 + h * 64 + d4 * 4];
  }
  for (int jc = 0; jc < 2; jc++) {
    __syncthreads();
#pragma unroll
    for (int it = 0; it < 8; it++) {
      int f = tid + it * 256, j = f >> 4, d4 = f & 15;
      *(float4*)&sWk[j * 68 + d4 * 4] =
          *(const float4*)&Wk[(size_t)(jc * 128 + j) * 256 + h * 64 + d4 * 4];
    }
    __syncthreads();
    int j = tid & 127, ih = tid >> 7;
#pragma unroll 1
    for (int il = ih * 8; il < ih * 8 + 8; il++) {
      float acc = 0.f;
#pragma unroll
      for (int d = 0; d < 64; d++) acc = fmaf(sWq[il * 68 + d], sWk[j * 68 + d], acc);
      g_Wcat[(size_t)(is * 16 + il) * 1280 + h * 256 + jc * 128 + j] = acc;
    }
  }
}

__global__ void copy_wres_kernel(const float* __restrict__ Wres) {
  g_Wcat[(size_t)blockIdx.x * 1280 + 1024 + threadIdx.x] =
      Wres[(size_t)blockIdx.x * 256 + threadIdx.x];
}

// ---------- SIMT GEMM, cp.async double-buffered, warp tile 16x128 ----------
// EPI: 0 store, 1 relu(x+bias), 2 LN(x+bias+resid) (gridDim.x==1)
template <int EPI>
__global__ void __launch_bounds__(256, 2) gemm_epi(
    const float* __restrict__ A, const float* __restrict__ W, float* __restrict__ C,
    int K, int ldw, int ldc, const float* __restrict__ bias,
    const float* __restrict__ resid, int ldres,
    const float* __restrict__ gamma, const float* __restrict__ beta) {
  extern __shared__ float smd[];
  float* sAT = smd;                 // [2][32*68]
  float* sB = smd + 2 * 32 * 68;    // [2][32*256]
  __shared__ float redS[128], redQ[128];
  int tid = threadIdx.x, lane = tid & 31, wid = tid >> 5;
  int rbase = (wid >> 1) * 16;
  int colslab = wid & 1;
  int cb = colslab * 128 + lane * 4;
  int m0 = blockIdx.y * 64, n0 = blockIdx.x * 256;
  unsigned long long acc[8][4];
#pragma unroll
  for (int i = 0; i < 8; i++)
#pragma unroll
    for (int j = 0; j < 4; j++) acc[i][j] = 0ull;

  uint32_t sBu = (uint32_t)__cvta_generic_to_shared(sB);
  int kt_n = K >> 5;
  float4 aR[2];
#pragma unroll
  for (int it = 0; it < 8; it++) {
    int f = tid + it * 256, kk = f >> 6, c4 = f & 63;
    cpa16(sBu + (kk * 256 + c4 * 4) * 4, &W[(size_t)kk * ldw + n0 + c4 * 4]);
  }
  CP_COMMIT();
#pragma unroll
  for (int it = 0; it < 2; it++) {
    int f = tid + it * 256, r = f >> 3, kq = f & 7;
    aR[it] = *(const float4*)&A[(size_t)(m0 + r) * K + kq * 4];
  }
#pragma unroll
  for (int it = 0; it < 2; it++) {
    int f = tid + it * 256, r = f >> 3, kq = f & 7;
    sAT[(kq * 4 + 0) * 68 + r] = aR[it].x;
    sAT[(kq * 4 + 1) * 68 + r] = aR[it].y;
    sAT[(kq * 4 + 2) * 68 + r] = aR[it].z;
    sAT[(kq * 4 + 3) * 68 + r] = aR[it].w;
  }
  CP_WAIT0();
  __syncthreads();

  for (int kt = 0; kt < kt_n; kt++) {
    int nb = (kt + 1) & 1;
    if (kt + 1 < kt_n) {
#pragma unroll
      for (int it = 0; it < 8; it++) {
        int f = tid + it * 256, kk = f >> 6, c4 = f & 63;
        cpa16(sBu + (nb * 32 * 256 + kk * 256 + c4 * 4) * 4,
              &W[(size_t)((kt + 1) * 32 + kk) * ldw + n0 + c4 * 4]);
      }
      CP_COMMIT();
#pragma unroll
      for (int it = 0; it < 2; it++) {
        int f = tid + it * 256, r = f >> 3, kq = f & 7;
        aR[it] = *(const float4*)&A[(size_t)(m0 + r) * K + (kt + 1) * 32 + kq * 4];
      }
    }
    const float* cA = sAT + (kt & 1) * 32 * 68;
    const float* cB = sB + (kt & 1) * 32 * 256;
#pragma unroll
    for (int kk = 0; kk < 32; kk++) {
      float4 bv = *(const float4*)&cB[kk * 256 + cb];
      unsigned long long bd0 = dup2(bv.x), bd1 = dup2(bv.y);
      unsigned long long bd2 = dup2(bv.z), bd3 = dup2(bv.w);
      const ulonglong2* ap = (const ulonglong2*)&cA[kk * 68 + rbase];
      ulonglong2 p0 = ap[0], p1 = ap[1], p2 = ap[2], p3 = ap[3];
      unsigned long long arr[8] = {p0.x, p0.y, p1.x, p1.y, p2.x, p2.y, p3.x, p3.y};
#pragma unroll
      for (int rp = 0; rp < 8; rp++) {
        FMA2(acc[rp][0], arr[rp], bd0);
        FMA2(acc[rp][1], arr[rp], bd1);
        FMA2(acc[rp][2], arr[rp], bd2);
        FMA2(acc[rp][3], arr[rp], bd3);
      }
    }
    if (kt + 1 < kt_n) {
      float* nA = sAT + nb * 32 * 68;
#pragma unroll
      for (int it = 0; it < 2; it++) {
        int f = tid + it * 256, r = f >> 3, kq = f & 7;
        nA[(kq * 4 + 0) * 68 + r] = aR[it].x;
        nA[(kq * 4 + 1) * 68 + r] = aR[it].y;
        nA[(kq * 4 + 2) * 68 + r] = aR[it].z;
        nA[(kq * 4 + 3) * 68 + r] = aR[it].w;
      }
      CP_WAIT0();
      __syncthreads();
    }
  }
  // ---- epilogue ----
  if (EPI == 2) {
    float v[16][4];
    float4 bv = *(const float4*)&bias[cb];
#pragma unroll
    for (int rp = 0; rp < 8; rp++) {
      float2 c0v = unpk(acc[rp][0]), c1v = unpk(acc[rp][1]);
      float2 c2v = unpk(acc[rp][2]), c3v = unpk(acc[rp][3]);
      float4 r0 = *(const float4*)&resid[(size_t)(m0 + rbase + 2 * rp) * ldres + cb];
      float4 r1 = *(const float4*)&resid[(size_t)(m0 + rbase + 2 * rp + 1) * ldres + cb];
      v[2 * rp][0] = c0v.x + bv.x + r0.x;
      v[2 * rp][1] = c1v.x + bv.y + r0.y;
      v[2 * rp][2] = c2v.x + bv.z + r0.z;
      v[2 * rp][3] = c3v.x + bv.w + r0.w;
      v[2 * rp + 1][0] = c0v.y + bv.x + r1.x;
      v[2 * rp + 1][1] = c1v.y + bv.y + r1.y;
      v[2 * rp + 1][2] = c2v.y + bv.z + r1.z;
      v[2 * rp + 1][3] = c3v.y + bv.w + r1.w;
    }
    ln_epilogue(v, rbase, colslab, cb, redS, redQ, gamma, beta, C, ldc, (size_t)m0);
    return;
  }
  float bb[4];
  if (EPI == 1) {
    float4 bv = *(const float4*)&bias[n0 + cb];
    bb[0] = bv.x; bb[1] = bv.y; bb[2] = bv.z; bb[3] = bv.w;
  }
#pragma unroll
  for (int rp = 0; rp < 8; rp++) {
    float2 c0v = unpk(acc[rp][0]), c1v = unpk(acc[rp][1]);
    float2 c2v = unpk(acc[rp][2]), c3v = unpk(acc[rp][3]);
    float4 o0 = {c0v.x, c1v.x, c2v.x, c3v.x};
    float4 o1 = {c0v.y, c1v.y, c2v.y, c3v.y};
    if (EPI == 1) {
      o0.x = fmaxf(o0.x + bb[0], 0.f); o0.y = fmaxf(o0.y + bb[1], 0.f);
      o0.z = fmaxf(o0.z + bb[2], 0.f); o0.w = fmaxf(o0.w + bb[3], 0.f);
      o1.x = fmaxf(o1.x + bb[0], 0.f); o1.y = fmaxf(o1.y + bb[1], 0.f);
      o1.z = fmaxf(o1.z + bb[2], 0.f); o1.w = fmaxf(o1.w + bb[3], 0.f);
    }
    *(float4*)&C[(size_t)(m0 + rbase + 2 * rp) * ldc + n0 + cb] = o0;
    *(float4*)&C[(size_t)(m0 + rbase + 2 * rp + 1) * ldc + n0 + cb] = o1;
  }
}

// ---------- K3: head-split GEMM + LN epilogue ----------
__global__ void __launch_bounds__(256, 2) gemm_hs(
    const float* __restrict__ Wv, float* __restrict__ C,
    const float* __restrict__ bias, const float* __restrict__ resid, int ldres,
    const float* __restrict__ gamma, const float* __restrict__ beta) {
  extern __shared__ float smd[];
  float* sAT = smd;                     // [2][16*4*68]
  float* sB = smd + 2 * 16 * 4 * 68;    // [2][16*256]
  __shared__ float redS[128], redQ[128];
  int tid = threadIdx.x, lane = tid & 31, wid = tid >> 5;
  int rbase = (wid >> 1) * 16;
  int colslab = wid & 1;
  int cb = colslab * 128 + lane * 4;
  int hl = colslab * 2 + (lane >> 4);
  int m0 = blockIdx.y * 64;
  unsigned long long acc[8][4];
#pragma unroll
  for (int i = 0; i < 8; i++)
#pragma unroll
    for (int j = 0; j < 4; j++) acc[i][j] = 0ull;

  uint32_t sBu = (uint32_t)__cvta_generic_to_shared(sB);
  float4 aR[4];
#pragma unroll
  for (int it = 0; it < 4; it++) {
    int f = tid + it * 256, kk = f >> 6, c4 = f & 63;
    cpa16(sBu + (kk * 256 + c4 * 4) * 4, &Wv[(size_t)kk * 256 + c4 * 4]);
  }
  CP_COMMIT();
#pragma unroll
  for (int it = 0; it < 4; it++) {
    int f = tid + it * 256, r = f >> 4, q = f & 15, h = q >> 2, kq = q & 3;
    aR[it] = *(const float4*)&g_U[(size_t)(m0 + r) * 1024 + h * 256 + kq * 4];
  }
#pragma unroll
  for (int it = 0; it < 4; it++) {
    int f = tid + it * 256, r = f >> 4, q = f & 15, h = q >> 2, kq = q & 3;
    sAT[((kq * 4 + 0) * 4 + h) * 68 + r] = aR[it].x;
    sAT[((kq * 4 + 1) * 4 + h) * 68 + r] = aR[it].y;
    sAT[((kq * 4 + 2) * 4 + h) * 68 + r] = aR[it].z;
    sAT[((kq * 4 + 3) * 4 + h) * 68 + r] = aR[it].w;
  }
  CP_WAIT0();
  __syncthreads();

  for (int kt = 0; kt < 16; kt++) {
    int nb = (kt + 1) & 1;
    if (kt + 1 < 16) {
#pragma unroll
      for (int it = 0; it < 4; it++) {
        int f = tid + it * 256, kk = f >> 6, c4 = f & 63;
        cpa16(sBu + (nb * 16 * 256 + kk * 256 + c4 * 4) * 4,
              &Wv[(size_t)((kt + 1) * 16 + kk) * 256 + c4 * 4]);
      }
      CP_COMMIT();
#pragma unroll
      for (int it = 0; it < 4; it++) {
        int f = tid + it * 256, r = f >> 4, q = f & 15, h = q >> 2, kq = q & 3;
        aR[it] = *(const float4*)&g_U[(size_t)(m0 + r) * 1024 + h * 256 +
                                      (kt + 1) * 16 + kq * 4];
      }
    }
    const float* cA = sAT + (kt & 1) * 16 * 4 * 68;
    const float* cB = sB + (kt & 1) * 16 * 256;
#pragma unroll
    for (int kk = 0; kk < 16; kk++) {
      float4 bv = *(const float4*)&cB[kk * 256 + cb];
      unsigned long long bd0 = dup2(bv.x), bd1 = dup2(bv.y);
      unsigned long long bd2 = dup2(bv.z), bd3 = dup2(bv.w);
      const ulonglong2* ap = (const ulonglong2*)&cA[(kk * 4 + hl) * 68 + rbase];
      ulonglong2 p0 = ap[0], p1 = ap[1], p2 = ap[2], p3 = ap[3];
      unsigned long long arr[8] = {p0.x, p0.y, p1.x, p1.y, p2.x, p2.y, p3.x, p3.y};
#pragma unroll
      for (int rp = 0; rp < 8; rp++) {
        FMA2(acc[rp][0], arr[rp], bd0);
        FMA2(acc[rp][1], arr[rp], bd1);
        FMA2(acc[rp][2], arr[rp], bd2);
        FMA2(acc[rp][3], arr[rp], bd3);
      }
    }
    if (kt + 1 < 16) {
      float* nA = sAT + nb * 16 * 4 * 68;
#pragma unroll
      for (int it = 0; it < 4; it++) {
        int f = tid + it * 256, r = f >> 4, q = f & 15, h = q >> 2, kq = q & 3;
        nA[((kq * 4 + 0) * 4 + h) * 68 + r] = aR[it].x;
        nA[((kq * 4 + 1) * 4 + h) * 68 + r] = aR[it].y;
        nA[((kq * 4 + 2) * 4 + h) * 68 + r] = aR[it].z;
        nA[((kq * 4 + 3) * 4 + h) * 68 + r] = aR[it].w;
      }
      CP_WAIT0();
      __syncthreads();
    }
  }
  float v[16][4];
  float4 bv = *(const float4*)&bias[cb];
#pragma unroll
  for (int rp = 0; rp < 8; rp++) {
    float2 c0v = unpk(acc[rp][0]), c1v = unpk(acc[rp][1]);
    float2 c2v = unpk(acc[rp][2]), c3v = unpk(acc[rp][3]);
    float4 r0 = *(const float4*)&resid[(size_t)(m0 + rbase + 2 * rp) * ldres + cb];
    float4 r1 = *(const float4*)&resid[(size_t)(m0 + rbase + 2 * rp + 1) * ldres + cb];
    v[2 * rp][0] = c0v.x + bv.x + r0.x;
    v[2 * rp][1] = c1v.x + bv.y + r0.y;
    v[2 * rp][2] = c2v.x + bv.z + r0.z;
    v[2 * rp][3] = c3v.x + bv.w + r0.w;
    v[2 * rp + 1][0] = c0v.y + bv.x + r1.x;
    v[2 * rp + 1][1] = c1v.y + bv.y + r1.y;
    v[2 * rp + 1][2] = c2v.y + bv.z + r1.z;
    v[2 * rp + 1][3] = c3v.y + bv.w + r1.w;
  }
  ln_epilogue(v, rbase, colslab, cb, redS, redQ, gamma, beta, C, 256, (size_t)m0);
}

// ---------------- K2: attention (FMA2 logits) ----------------
__global__ void __launch_bounds__(256) attn_u_kernel(
    const float* __restrict__ x_ctx, const float* __restrict__ t_ctx,
    const float* __restrict__ freq, const float* __restrict__ phase) {
  __shared__ float kv[32 * 260];
  __shared__ float p2[4 * 8 * 36];
  __shared__ float slog[128];
  __shared__ __align__(16) float sw[128];
  __shared__ float sfr[64], sph[64];
  int b = blockIdx.x, tid = threadIdx.x;
  int l = tid >> 3, sub = tid & 7;

  if (tid < 64) {
    sfr[tid] = freq[tid];
    sph[tid] = phase[tid];
  }
  {
    int h = tid >> 6, r = tid & 63, s2 = r >> 3, c = r & 7;
    int idx4;
    if (c < 4) idx4 = h * 64 + s2 * 4 + c;
    else if (c < 6) idx4 = h * 64 + 32 + s2 * 2 + (c - 4);
    else idx4 = h * 64 + 48 + s2 * 2 + (c - 6);
    float4 v = *(const float4*)&g_PR[(size_t)b * 1280 + (size_t)idx4 * 4];
    *(float4*)&p2[(h * 8 + s2) * 36 + c * 4] = v;
  }
  __syncthreads();

  unsigned long long accP[4] = {0ull, 0ull, 0ull, 0ull};
  const float* xsrc = x_ctx + ((size_t)b * 32 + l) * 128 + sub * 16;
  float* kvrow = kv + l * 260;

  // x-part: LDG as pairs -> swizzled STS -> FMA2 vs p2 pairs
#pragma unroll
  for (int c = 0; c < 4; c++) {
    ulonglong2 vv = *(const ulonglong2*)&xsrc[c * 4];
    *(ulonglong2*)&kvrow[SW(sub * 16 + c * 4)] = vv;
#pragma unroll
    for (int h = 0; h < 4; h++) {
      ulonglong2 pp = *(const ulonglong2*)&p2[(h * 8 + sub) * 36 + c * 4];
      FMA2(accP[h], vv.x, pp.x);
      FMA2(accP[h], vv.y, pp.y);
    }
  }
  // te-part
  {
    float t = t_ctx[(size_t)b * 32 + l];
    float lt = log1pf(fmaxf(t, 0.f));
#pragma unroll
    for (int g = 0; g < 2; g++) {
      float s0, c0, s1, c1, s2, c2, s3, c3;
      int k0 = sub * 8 + g * 4;
      fast_sincos(fmaf(lt, sfr[k0 + 0], sph[k0 + 0]), s0, c0);
      fast_sincos(fmaf(lt, sfr[k0 + 1], sph[k0 + 1]), s1, c1);
      fast_sincos(fmaf(lt, sfr[k0 + 2], sph[k0 + 2]), s2, c2);
      fast_sincos(fmaf(lt, sfr[k0 + 3], sph[k0 + 3]), s3, c3);
      ulonglong2 sp2 = {pk2(s0, s1), pk2(s2, s3)};
      ulonglong2 cp2 = {pk2(c0, c1), pk2(c2, c3)};
      *(ulonglong2*)&kvrow[SW(128 + sub * 8 + g * 4)] = sp2;
      *(ulonglong2*)&kvrow[SW(192 + sub * 8 + g * 4)] = cp2;
#pragma unroll
      for (int h = 0; h < 4; h++) {
        ulonglong2 ps = *(const ulonglong2*)&p2[(h * 8 + sub) * 36 + (4 + g) * 4];
        ulonglong2 pc = *(const ulonglong2*)&p2[(h * 8 + sub) * 36 + (6 + g) * 4];
        FMA2(accP[h], sp2.x, ps.x);
        FMA2(accP[h], sp2.y, ps.y);
        FMA2(accP[h], cp2.x, pc.x);
        FMA2(accP[h], cp2.y, pc.y);
      }
    }
  }
  float acc[4];
#pragma unroll
  for (int h = 0; h < 4; h++) {
    float2 u = unpk(accP[h]);
    acc[h] = u.x + u.y;
#pragma unroll
    for (int o = 4; o; o >>= 1) acc[h] += __shfl_xor_sync(0xffffffffu, acc[h], o);
  }
  if (sub < 4) slog[sub * 32 + l] = acc[sub] * 0.125f;
  __syncthreads();
  if (tid < 128) {
    int h = tid >> 5, ll = tid & 31;
    float v = slog[tid];
    float m = wmax(v);
    float e = __expf(v - m);
    float s = wsum(e);
    sw[ll * 4 + h] = e / s;
  }
  __syncthreads();
  if (tid < 64) {
    int j0 = tid * 4;
    int sj = SW(j0);
    unsigned long long au[4][2];
#pragma unroll
    for (int d = 0; d < 4; d++) { au[d][0] = 0ull; au[d][1] = 0ull; }
#pragma unroll
    for (int ll = 0; ll < 32; ll++) {
      float4 kq = *(const float4*)&kv[ll * 260 + sj];
      ulonglong2 w2 = *(const ulonglong2*)&sw[ll * 4];
      unsigned long long d0 = dup2(kq.x), d1 = dup2(kq.y);
      unsigned long long d2 = dup2(kq.z), d3 = dup2(kq.w);
      FMA2(au[0][0], d0, w2.x); FMA2(au[0][1], d0, w2.y);
      FMA2(au[1][0], d1, w2.x); FMA2(au[1][1], d1, w2.y);
      FMA2(au[2][0], d2, w2.x); FMA2(au[2][1], d2, w2.y);
      FMA2(au[3][0], d3, w2.x); FMA2(au[3][1], d3, w2.y);
    }
    float2 p01[4], p23[4];
#pragma unroll
    for (int d = 0; d < 4; d++) {
      p01[d] = unpk(au[d][0]);
      p23[d] = unpk(au[d][1]);
    }
    size_t o = (size_t)b * 1024 + j0;
    float4 u0 = {p01[0].x, p01[1].x, p01[2].x, p01[3].x};
    float4 u1 = {p01[0].y, p01[1].y, p01[2].y, p01[3].y};
    float4 u2 = {p23[0].x, p23[1].x, p23[2].x, p23[3].x};
    float4 u3 = {p23[0].y, p23[1].y, p23[2].y, p23[3].y};
    *(float4*)&g_U[o] = u0;
    *(float4*)&g_U[o + 256] = u1;
    *(float4*)&g_U[o + 512] = u2;
    *(float4*)&g_U[o + 768] = u3;
  }
}

// ---------------- launch ----------------
extern "C" void kernel_launch(void* const* d_in, const int* in_sizes, int n_in,
                              void* d_out, int out_size) {
  const float* x_u   = (const float*)d_in[0];
  const float* x_ctx = (const float*)d_in[1];
  const float* t_ctx = (const float*)d_in[2];
  const float* freq  = (const float*)d_in[3];
  const float* phase = (const float*)d_in[4];
  const float* Wq    = (const float*)d_in[5];
  const float* Wk    = (const float*)d_in[6];
  const float* Wv    = (const float*)d_in[7];
  const float* Wres  = (const float*)d_in[8];
  const float* bres  = (const float*)d_in[9];
  const float* W1    = (const float*)d_in[10];
  const float* b1    = (const float*)d_in[11];
  const float* W2    = (const float*)d_in[12];
  const float* b2    = (const float*)d_in[13];
  const float* g1    = (const float*)d_in[14];
  const float* be1   = (const float*)d_in[15];
  const float* g2    = (const float*)d_in[16];
  const float* be2   = (const float*)d_in[17];
  float* out = (float*)d_out;

  float *pWcat, *pPR, *pZ1, *pH1;
  cudaGetSymbolAddress((void**)&pWcat, g_Wcat);
  cudaGetSymbolAddress((void**)&pPR, g_PR);
  cudaGetSymbolAddress((void**)&pZ1, g_Z1);
  cudaGetSymbolAddress((void**)&pH1, g_H1);

  int smemEpi = (2 * 32 * 68 + 2 * 32 * 256) * 4;     // 82,944 B
  int smemHs = (2 * 16 * 4 * 68 + 2 * 16 * 256) * 4;  // 67,584 B
  cudaFuncSetAttribute(gemm_epi<0>, cudaFuncAttributeMaxDynamicSharedMemorySize, smemEpi);
  cudaFuncSetAttribute(gemm_epi<1>, cudaFuncAttributeMaxDynamicSharedMemorySize, smemEpi);
  cudaFuncSetAttribute(gemm_epi<2>, cudaFuncAttributeMaxDynamicSharedMemorySize, smemEpi);
  cudaFuncSetAttribute(gemm_hs, cudaFuncAttributeMaxDynamicSharedMemorySize, smemHs);

  mqk_kernel<<<dim3(4, 8), 256>>>(Wq, Wk);
  copy_wres_kernel<<<128, 256>>>(Wres);

  // K1: P|R = x_u @ Wcat
  gemm_epi<0><<<dim3(5, 256), 256, smemEpi>>>(x_u, pWcat, pPR, 128, 1280, 1280,
                                              nullptr, nullptr, 0, nullptr, nullptr);

  // K2: attention -> u
  attn_u_kernel<<<BB, 256>>>(x_ctx, t_ctx, freq, phase);

  // K3: z1 = LN(u_h @ Wv_h + R + bres)
  gemm_hs<<<dim3(1, 256), 256, smemHs>>>(Wv, pZ1, bres, pPR + 1024, 1280, g1, be1);

  // K4: h1 = relu(z1 @ W1 + b1)
  gemm_epi<1><<<dim3(1, 256), 256, smemEpi>>>(pZ1, W1, pH1, 256, 256, 256,
                                              b1, nullptr, 0, nullptr, nullptr);

  // K5: out = LN(h1 @ W2 + b2 + z1)
  gemm_epi<2><<<dim3(1, 256), 256, smemEpi>>>(pH1, W2, out, 256, 256, 256,
                                              b2, pZ1, 256, g2, be2);
}

// round 15
// speedup vs baseline: 1.0483x; 1.0483x over previous
#include <cuda_runtime.h>
#include <math.h>
#include <stdint.h>

#define BB 16384

__device__ __align__(16) float g_Wcat[128 * 1280];
__device__ __align__(16) float g_PR[(size_t)BB * 1280];
__device__ __align__(16) float g_U[(size_t)BB * 1024];
__device__ __align__(16) float g_Z1[(size_t)BB * 256];
__device__ __align__(16) float g_H1[(size_t)BB * 256];

__device__ __forceinline__ float wsum(float v) {
#pragma unroll
  for (int o = 16; o; o >>= 1) v += __shfl_xor_sync(0xffffffffu, v, o);
  return v;
}
__device__ __forceinline__ float wmax(float v) {
#pragma unroll
  for (int o = 16; o; o >>= 1) v = fmaxf(v, __shfl_xor_sync(0xffffffffu, v, o));
  return v;
}

#define FMA2(d, a, b) \
  asm("fma.rn.f32x2 %0, %1, %2, %0;" : "+l"(d) : "l"(a), "l"(b))
__device__ __forceinline__ unsigned long long dup2(float x) {
  unsigned long long r;
  asm("mov.b64 %0, {%1, %1};" : "=l"(r) : "f"(x));
  return r;
}
__device__ __forceinline__ float2 unpk(unsigned long long p) {
  float2 r;
  asm("mov.b64 {%0, %1}, %2;" : "=f"(r.x), "=f"(r.y) : "l"(p));
  return r;
}
__device__ __forceinline__ void cpa16(uint32_t s, const void* g) {
  asm volatile("cp.async.cg.shared.global [%0], [%1], 16;" :: "r"(s), "l"(g));
}
#define CP_COMMIT() asm volatile("cp.async.commit_group;" ::: "memory")
#define CP_WAIT0() asm volatile("cp.async.wait_group 0;" ::: "memory")

__device__ __forceinline__ int SW(int d) {
  return (d & ~31) | ((d & 31) ^ (((d >> 5) & 3) << 2));
}

__device__ __forceinline__ void fast_sincos(float z, float& s, float& c) {
  float t = rintf(z * 0.63661977236758134f);
  int qi = (int)t;
  float r = fmaf(t, -1.5703125f, z);
  r = fmaf(t, -4.83751296997070312e-4f, r);
  r = fmaf(t, -7.54978995489188e-8f, r);
  float r2 = r * r;
  float sp = fmaf(r2, -1.9515296e-4f, 8.3321608e-3f);
  sp = fmaf(r2, sp, -1.6666654611e-1f);
  float sinr = fmaf(r * r2, sp, r);
  float cp = fmaf(r2, -1.388731625493765e-3f, 4.166664568298827e-2f);
  cp = fmaf(r2, cp, -0.5f);
  float cosr = fmaf(r2, cp, 1.0f);
  int qq = qi & 3;
  float ss = (qq & 1) ? cosr : sinr;
  float cc = (qq & 1) ? sinr : cosr;
  s = (qq & 2) ? -ss : ss;
  c = ((qq + 1) & 2) ? -cc : cc;
}

// per-warp LN helper (proven)
__device__ __forceinline__ void ln_epilogue(
    float (*v)[4], int rbase, int colslab, int cb,
    float* redS, float* redQ,
    const float* gamma, const float* beta, float* C, int ldc, size_t m0) {
  int lane = threadIdx.x & 31;
#pragma unroll
  for (int r = 0; r < 16; r++) {
    float s = v[r][0] + v[r][1] + v[r][2] + v[r][3];
    float q = v[r][0] * v[r][0] + v[r][1] * v[r][1] +
              v[r][2] * v[r][2] + v[r][3] * v[r][3];
    s = wsum(s);
    q = wsum(q);
    if (lane == 0) {
      redS[colslab * 64 + rbase + r] = s;
      redQ[colslab * 64 + rbase + r] = q;
    }
  }
  __syncthreads();
  float4 gg = *(const float4*)&gamma[cb];
  float4 ee = *(const float4*)&beta[cb];
#pragma unroll
  for (int r = 0; r < 16; r++) {
    float s = redS[rbase + r] + redS[64 + rbase + r];
    float q = redQ[rbase + r] + redQ[64 + rbase + r];
    float mean = s * (1.f / 256.f);
    float var = fmaf(-mean, mean, q * (1.f / 256.f));
    float rstd = rsqrtf(var + 1e-5f);
    float4 o;
    o.x = (v[r][0] - mean) * rstd * gg.x + ee.x;
    o.y = (v[r][1] - mean) * rstd * gg.y + ee.y;
    o.z = (v[r][2] - mean) * rstd * gg.z + ee.z;
    o.w = (v[r][3] - mean) * rstd * gg.w + ee.w;
    *(float4*)&C[(m0 + rbase + r) * ldc + cb] = o;
  }
}

// ---------------- K0 ----------------
__global__ void __launch_bounds__(256) mqk_kernel(const float* __restrict__ Wq,
                                                  const float* __restrict__ Wk) {
  __shared__ float sWq[16 * 68];
  __shared__ float sWk[128 * 68];
  int h = blockIdx.x, is = blockIdx.y, tid = threadIdx.x;
  {
    int il = tid >> 4, d4 = tid & 15;
    *(float4*)&sWq[il * 68 + d4 * 4] =
        *(const float4*)&Wq[(size_t)(is * 16 + il) * 256 + h * 64 + d4 * 4];
  }
  for (int jc = 0; jc < 2; jc++) {
    __syncthreads();
#pragma unroll
    for (int it = 0; it < 8; it++) {
      int f = tid + it * 256, j = f >> 4, d4 = f & 15;
      *(float4*)&sWk[j * 68 + d4 * 4] =
          *(const float4*)&Wk[(size_t)(jc * 128 + j) * 256 + h * 64 + d4 * 4];
    }
    __syncthreads();
    int j = tid & 127, ih = tid >> 7;
#pragma unroll 1
    for (int il = ih * 8; il < ih * 8 + 8; il++) {
      float acc = 0.f;
#pragma unroll
      for (int d = 0; d < 64; d++) acc = fmaf(sWq[il * 68 + d], sWk[j * 68 + d], acc);
      g_Wcat[(size_t)(is * 16 + il) * 1280 + h * 256 + jc * 128 + j] = acc;
    }
  }
}

__global__ void copy_wres_kernel(const float* __restrict__ Wres) {
  g_Wcat[(size_t)blockIdx.x * 1280 + 1024 + threadIdx.x] =
      Wres[(size_t)blockIdx.x * 256 + threadIdx.x];
}

// ---------- SIMT GEMM, cp.async double-buffered, warp tile 16x128 ----------
// EPI: 0 store, 1 relu(x+bias), 2 LN(x+bias+resid) (gridDim.x==1)
template <int EPI>
__global__ void __launch_bounds__(256, 2) gemm_epi(
    const float* __restrict__ A, const float* __restrict__ W, float* __restrict__ C,
    int K, int ldw, int ldc, const float* __restrict__ bias,
    const float* __restrict__ resid, int ldres,
    const float* __restrict__ gamma, const float* __restrict__ beta) {
  extern __shared__ float smd[];
  float* sAT = smd;                 // [2][32*68]
  float* sB = smd + 2 * 32 * 68;    // [2][32*256]
  __shared__ float redS[128], redQ[128];
  int tid = threadIdx.x, lane = tid & 31, wid = tid >> 5;
  int rbase = (wid >> 1) * 16;
  int colslab = wid & 1;
  int cb = colslab * 128 + lane * 4;
  int m0 = blockIdx.y * 64, n0 = blockIdx.x * 256;
  unsigned long long acc[8][4];
#pragma unroll
  for (int i = 0; i < 8; i++)
#pragma unroll
    for (int j = 0; j < 4; j++) acc[i][j] = 0ull;

  uint32_t sBu = (uint32_t)__cvta_generic_to_shared(sB);
  int kt_n = K >> 5;
  float4 aR[2];
#pragma unroll
  for (int it = 0; it < 8; it++) {
    int f = tid + it * 256, kk = f >> 6, c4 = f & 63;
    cpa16(sBu + (kk * 256 + c4 * 4) * 4, &W[(size_t)kk * ldw + n0 + c4 * 4]);
  }
  CP_COMMIT();
#pragma unroll
  for (int it = 0; it < 2; it++) {
    int f = tid + it * 256, r = f >> 3, kq = f & 7;
    aR[it] = *(const float4*)&A[(size_t)(m0 + r) * K + kq * 4];
  }
#pragma unroll
  for (int it = 0; it < 2; it++) {
    int f = tid + it * 256, r = f >> 3, kq = f & 7;
    sAT[(kq * 4 + 0) * 68 + r] = aR[it].x;
    sAT[(kq * 4 + 1) * 68 + r] = aR[it].y;
    sAT[(kq * 4 + 2) * 68 + r] = aR[it].z;
    sAT[(kq * 4 + 3) * 68 + r] = aR[it].w;
  }
  CP_WAIT0();
  __syncthreads();

  for (int kt = 0; kt < kt_n; kt++) {
    int nb = (kt + 1) & 1;
    if (kt + 1 < kt_n) {
#pragma unroll
      for (int it = 0; it < 8; it++) {
        int f = tid + it * 256, kk = f >> 6, c4 = f & 63;
        cpa16(sBu + (nb * 32 * 256 + kk * 256 + c4 * 4) * 4,
              &W[(size_t)((kt + 1) * 32 + kk) * ldw + n0 + c4 * 4]);
      }
      CP_COMMIT();
#pragma unroll
      for (int it = 0; it < 2; it++) {
        int f = tid + it * 256, r = f >> 3, kq = f & 7;
        aR[it] = *(const float4*)&A[(size_t)(m0 + r) * K + (kt + 1) * 32 + kq * 4];
      }
    }
    const float* cA = sAT + (kt & 1) * 32 * 68;
    const float* cB = sB + (kt & 1) * 32 * 256;
#pragma unroll
    for (int kk = 0; kk < 32; kk++) {
      float4 bv = *(const float4*)&cB[kk * 256 + cb];
      unsigned long long bd0 = dup2(bv.x), bd1 = dup2(bv.y);
      unsigned long long bd2 = dup2(bv.z), bd3 = dup2(bv.w);
      const ulonglong2* ap = (const ulonglong2*)&cA[kk * 68 + rbase];
      ulonglong2 p0 = ap[0], p1 = ap[1], p2 = ap[2], p3 = ap[3];
      unsigned long long arr[8] = {p0.x, p0.y, p1.x, p1.y, p2.x, p2.y, p3.x, p3.y};
#pragma unroll
      for (int rp = 0; rp < 8; rp++) {
        FMA2(acc[rp][0], arr[rp], bd0);
        FMA2(acc[rp][1], arr[rp], bd1);
        FMA2(acc[rp][2], arr[rp], bd2);
        FMA2(acc[rp][3], arr[rp], bd3);
      }
    }
    if (kt + 1 < kt_n) {
      float* nA = sAT + nb * 32 * 68;
#pragma unroll
      for (int it = 0; it < 2; it++) {
        int f = tid + it * 256, r = f >> 3, kq = f & 7;
        nA[(kq * 4 + 0) * 68 + r] = aR[it].x;
        nA[(kq * 4 + 1) * 68 + r] = aR[it].y;
        nA[(kq * 4 + 2) * 68 + r] = aR[it].z;
        nA[(kq * 4 + 3) * 68 + r] = aR[it].w;
      }
      CP_WAIT0();
      __syncthreads();
    }
  }
  // ---- epilogue ----
  if (EPI == 2) {
    float v[16][4];
    float4 bv = *(const float4*)&bias[cb];
#pragma unroll
    for (int rp = 0; rp < 8; rp++) {
      float2 c0v = unpk(acc[rp][0]), c1v = unpk(acc[rp][1]);
      float2 c2v = unpk(acc[rp][2]), c3v = unpk(acc[rp][3]);
      float4 r0 = *(const float4*)&resid[(size_t)(m0 + rbase + 2 * rp) * ldres + cb];
      float4 r1 = *(const float4*)&resid[(size_t)(m0 + rbase + 2 * rp + 1) * ldres + cb];
      v[2 * rp][0] = c0v.x + bv.x + r0.x;
      v[2 * rp][1] = c1v.x + bv.y + r0.y;
      v[2 * rp][2] = c2v.x + bv.z + r0.z;
      v[2 * rp][3] = c3v.x + bv.w + r0.w;
      v[2 * rp + 1][0] = c0v.y + bv.x + r1.x;
      v[2 * rp + 1][1] = c1v.y + bv.y + r1.y;
      v[2 * rp + 1][2] = c2v.y + bv.z + r1.z;
      v[2 * rp + 1][3] = c3v.y + bv.w + r1.w;
    }
    ln_epilogue(v, rbase, colslab, cb, redS, redQ, gamma, beta, C, ldc, (size_t)m0);
    return;
  }
  float bb[4];
  if (EPI == 1) {
    float4 bv = *(const float4*)&bias[n0 + cb];
    bb[0] = bv.x; bb[1] = bv.y; bb[2] = bv.z; bb[3] = bv.w;
  }
#pragma unroll
  for (int rp = 0; rp < 8; rp++) {
    float2 c0v = unpk(acc[rp][0]), c1v = unpk(acc[rp][1]);
    float2 c2v = unpk(acc[rp][2]), c3v = unpk(acc[rp][3]);
    float4 o0 = {c0v.x, c1v.x, c2v.x, c3v.x};
    float4 o1 = {c0v.y, c1v.y, c2v.y, c3v.y};
    if (EPI == 1) {
      o0.x = fmaxf(o0.x + bb[0], 0.f); o0.y = fmaxf(o0.y + bb[1], 0.f);
      o0.z = fmaxf(o0.z + bb[2], 0.f); o0.w = fmaxf(o0.w + bb[3], 0.f);
      o1.x = fmaxf(o1.x + bb[0], 0.f); o1.y = fmaxf(o1.y + bb[1], 0.f);
      o1.z = fmaxf(o1.z + bb[2], 0.f); o1.w = fmaxf(o1.w + bb[3], 0.f);
    }
    *(float4*)&C[(size_t)(m0 + rbase + 2 * rp) * ldc + n0 + cb] = o0;
    *(float4*)&C[(size_t)(m0 + rbase + 2 * rp + 1) * ldc + n0 + cb] = o1;
  }
}

// ---------- K3: head-split GEMM + LN epilogue ----------
__global__ void __launch_bounds__(256, 2) gemm_hs(
    const float* __restrict__ Wv, float* __restrict__ C,
    const float* __restrict__ bias, const float* __restrict__ resid, int ldres,
    const float* __restrict__ gamma, const float* __restrict__ beta) {
  extern __shared__ float smd[];
  float* sAT = smd;                     // [2][16*4*68]
  float* sB = smd + 2 * 16 * 4 * 68;    // [2][16*256]
  __shared__ float redS[128], redQ[128];
  int tid = threadIdx.x, lane = tid & 31, wid = tid >> 5;
  int rbase = (wid >> 1) * 16;
  int colslab = wid & 1;
  int cb = colslab * 128 + lane * 4;
  int hl = colslab * 2 + (lane >> 4);
  int m0 = blockIdx.y * 64;
  unsigned long long acc[8][4];
#pragma unroll
  for (int i = 0; i < 8; i++)
#pragma unroll
    for (int j = 0; j < 4; j++) acc[i][j] = 0ull;

  uint32_t sBu = (uint32_t)__cvta_generic_to_shared(sB);
  float4 aR[4];
#pragma unroll
  for (int it = 0; it < 4; it++) {
    int f = tid + it * 256, kk = f >> 6, c4 = f & 63;
    cpa16(sBu + (kk * 256 + c4 * 4) * 4, &Wv[(size_t)kk * 256 + c4 * 4]);
  }
  CP_COMMIT();
#pragma unroll
  for (int it = 0; it < 4; it++) {
    int f = tid + it * 256, r = f >> 4, q = f & 15, h = q >> 2, kq = q & 3;
    aR[it] = *(const float4*)&g_U[(size_t)(m0 + r) * 1024 + h * 256 + kq * 4];
  }
#pragma unroll
  for (int it = 0; it < 4; it++) {
    int f = tid + it * 256, r = f >> 4, q = f & 15, h = q >> 2, kq = q & 3;
    sAT[((kq * 4 + 0) * 4 + h) * 68 + r] = aR[it].x;
    sAT[((kq * 4 + 1) * 4 + h) * 68 + r] = aR[it].y;
    sAT[((kq * 4 + 2) * 4 + h) * 68 + r] = aR[it].z;
    sAT[((kq * 4 + 3) * 4 + h) * 68 + r] = aR[it].w;
  }
  CP_WAIT0();
  __syncthreads();

  for (int kt = 0; kt < 16; kt++) {
    int nb = (kt + 1) & 1;
    if (kt + 1 < 16) {
#pragma unroll
      for (int it = 0; it < 4; it++) {
        int f = tid + it * 256, kk = f >> 6, c4 = f & 63;
        cpa16(sBu + (nb * 16 * 256 + kk * 256 + c4 * 4) * 4,
              &Wv[(size_t)((kt + 1) * 16 + kk) * 256 + c4 * 4]);
      }
      CP_COMMIT();
#pragma unroll
      for (int it = 0; it < 4; it++) {
        int f = tid + it * 256, r = f >> 4, q = f & 15, h = q >> 2, kq = q & 3;
        aR[it] = *(const float4*)&g_U[(size_t)(m0 + r) * 1024 + h * 256 +
                                      (kt + 1) * 16 + kq * 4];
      }
    }
    const float* cA = sAT + (kt & 1) * 16 * 4 * 68;
    const float* cB = sB + (kt & 1) * 16 * 256;
#pragma unroll
    for (int kk = 0; kk < 16; kk++) {
      float4 bv = *(const float4*)&cB[kk * 256 + cb];
      unsigned long long bd0 = dup2(bv.x), bd1 = dup2(bv.y);
      unsigned long long bd2 = dup2(bv.z), bd3 = dup2(bv.w);
      const ulonglong2* ap = (const ulonglong2*)&cA[(kk * 4 + hl) * 68 + rbase];
      ulonglong2 p0 = ap[0], p1 = ap[1], p2 = ap[2], p3 = ap[3];
      unsigned long long arr[8] = {p0.x, p0.y, p1.x, p1.y, p2.x, p2.y, p3.x, p3.y};
#pragma unroll
      for (int rp = 0; rp < 8; rp++) {
        FMA2(acc[rp][0], arr[rp], bd0);
        FMA2(acc[rp][1], arr[rp], bd1);
        FMA2(acc[rp][2], arr[rp], bd2);
        FMA2(acc[rp][3], arr[rp], bd3);
      }
    }
    if (kt + 1 < 16) {
      float* nA = sAT + nb * 16 * 4 * 68;
#pragma unroll
      for (int it = 0; it < 4; it++) {
        int f = tid + it * 256, r = f >> 4, q = f & 15, h = q >> 2, kq = q & 3;
        nA[((kq * 4 + 0) * 4 + h) * 68 + r] = aR[it].x;
        nA[((kq * 4 + 1) * 4 + h) * 68 + r] = aR[it].y;
        nA[((kq * 4 + 2) * 4 + h) * 68 + r] = aR[it].z;
        nA[((kq * 4 + 3) * 4 + h) * 68 + r] = aR[it].w;
      }
      CP_WAIT0();
      __syncthreads();
    }
  }
  float v[16][4];
  float4 bv = *(const float4*)&bias[cb];
#pragma unroll
  for (int rp = 0; rp < 8; rp++) {
    float2 c0v = unpk(acc[rp][0]), c1v = unpk(acc[rp][1]);
    float2 c2v = unpk(acc[rp][2]), c3v = unpk(acc[rp][3]);
    float4 r0 = *(const float4*)&resid[(size_t)(m0 + rbase + 2 * rp) * ldres + cb];
    float4 r1 = *(const float4*)&resid[(size_t)(m0 + rbase + 2 * rp + 1) * ldres + cb];
    v[2 * rp][0] = c0v.x + bv.x + r0.x;
    v[2 * rp][1] = c1v.x + bv.y + r0.y;
    v[2 * rp][2] = c2v.x + bv.z + r0.z;
    v[2 * rp][3] = c3v.x + bv.w + r0.w;
    v[2 * rp + 1][0] = c0v.y + bv.x + r1.x;
    v[2 * rp + 1][1] = c1v.y + bv.y + r1.y;
    v[2 * rp + 1][2] = c2v.y + bv.z + r1.z;
    v[2 * rp + 1][3] = c3v.y + bv.w + r1.w;
  }
  ln_epilogue(v, rbase, colslab, cb, redS, redQ, gamma, beta, C, 256, (size_t)m0);
}

// ---------------- K2: attention (R11 logits, 4-warp u-phase) ----------------
__global__ void __launch_bounds__(256) attn_u_kernel(
    const float* __restrict__ x_ctx, const float* __restrict__ t_ctx,
    const float* __restrict__ freq, const float* __restrict__ phase) {
  __shared__ float kv[32 * 260];
  __shared__ float p2[4 * 8 * 36];
  __shared__ float slog[128];
  __shared__ __align__(16) float sw[128];
  __shared__ float sfr[64], sph[64];
  int b = blockIdx.x, tid = threadIdx.x;
  int l = tid >> 3, sub = tid & 7;

  if (tid < 64) {
    sfr[tid] = freq[tid];
    sph[tid] = phase[tid];
  }
  {
    int h = tid >> 6, r = tid & 63, s2 = r >> 3, c = r & 7;
    int idx4;
    if (c < 4) idx4 = h * 64 + s2 * 4 + c;
    else if (c < 6) idx4 = h * 64 + 32 + s2 * 2 + (c - 4);
    else idx4 = h * 64 + 48 + s2 * 2 + (c - 6);
    float4 v = *(const float4*)&g_PR[(size_t)b * 1280 + (size_t)idx4 * 4];
    *(float4*)&p2[(h * 8 + s2) * 36 + c * 4] = v;
  }
  __syncthreads();

  float acc[4] = {0.f, 0.f, 0.f, 0.f};
  const float* xsrc = x_ctx + ((size_t)b * 32 + l) * 128 + sub * 16;
  float* kvrow = kv + l * 260;

#pragma unroll
  for (int c = 0; c < 4; c++) {
    float4 v = *(const float4*)&xsrc[c * 4];
    *(float4*)&kvrow[SW(sub * 16 + c * 4)] = v;
#pragma unroll
    for (int h = 0; h < 4; h++) {
      float4 p = *(const float4*)&p2[(h * 8 + sub) * 36 + c * 4];
      acc[h] = fmaf(v.x, p.x, acc[h]);
      acc[h] = fmaf(v.y, p.y, acc[h]);
      acc[h] = fmaf(v.z, p.z, acc[h]);
      acc[h] = fmaf(v.w, p.w, acc[h]);
    }
  }
  {
    float t = t_ctx[(size_t)b * 32 + l];
    float lt = log1pf(fmaxf(t, 0.f));
#pragma unroll
    for (int g = 0; g < 2; g++) {
      float4 sv, cv;
      float ss, cc;
      int k0 = sub * 8 + g * 4;
      float z0 = fmaf(lt, sfr[k0 + 0], sph[k0 + 0]);
      float z1 = fmaf(lt, sfr[k0 + 1], sph[k0 + 1]);
      float z2 = fmaf(lt, sfr[k0 + 2], sph[k0 + 2]);
      float z3 = fmaf(lt, sfr[k0 + 3], sph[k0 + 3]);
      fast_sincos(z0, ss, cc); sv.x = ss; cv.x = cc;
      fast_sincos(z1, ss, cc); sv.y = ss; cv.y = cc;
      fast_sincos(z2, ss, cc); sv.z = ss; cv.z = cc;
      fast_sincos(z3, ss, cc); sv.w = ss; cv.w = cc;
      *(float4*)&kvrow[SW(128 + sub * 8 + g * 4)] = sv;
      *(float4*)&kvrow[SW(192 + sub * 8 + g * 4)] = cv;
#pragma unroll
      for (int h = 0; h < 4; h++) {
        float4 ps = *(const float4*)&p2[(h * 8 + sub) * 36 + (4 + g) * 4];
        float4 pc = *(const float4*)&p2[(h * 8 + sub) * 36 + (6 + g) * 4];
        acc[h] = fmaf(sv.x, ps.x, acc[h]);
        acc[h] = fmaf(sv.y, ps.y, acc[h]);
        acc[h] = fmaf(sv.z, ps.z, acc[h]);
        acc[h] = fmaf(sv.w, ps.w, acc[h]);
        acc[h] = fmaf(cv.x, pc.x, acc[h]);
        acc[h] = fmaf(cv.y, pc.y, acc[h]);
        acc[h] = fmaf(cv.z, pc.z, acc[h]);
        acc[h] = fmaf(cv.w, pc.w, acc[h]);
      }
    }
  }
#pragma unroll
  for (int h = 0; h < 4; h++) {
#pragma unroll
    for (int o = 4; o; o >>= 1) acc[h] += __shfl_xor_sync(0xffffffffu, acc[h], o);
  }
  if (sub < 4) slog[sub * 32 + l] = acc[sub] * 0.125f;
  __syncthreads();
  if (tid < 128) {
    int h = tid >> 5, ll = tid & 31;
    float v = slog[tid];
    float m = wmax(v);
    float e = __expf(v - m);
    float s = wsum(e);
    sw[ll * 4 + h] = e / s;
  }
  __syncthreads();
  // u-phase: 128 threads, thread owns dims j0..j0+1 (float2), all 4 heads
  if (tid < 128) {
    int j0 = tid * 2;
    int sj = SW(j0);  // 8B-aligned, contiguous pair (SW flips word bits 2-3 only)
    unsigned long long au[2][2];
    au[0][0] = 0ull; au[0][1] = 0ull;
    au[1][0] = 0ull; au[1][1] = 0ull;
#pragma unroll
    for (int ll = 0; ll < 32; ll++) {
      float2 kq = *(const float2*)&kv[ll * 260 + sj];
      ulonglong2 w2 = *(const ulonglong2*)&sw[ll * 4];
      unsigned long long d0 = dup2(kq.x), d1 = dup2(kq.y);
      FMA2(au[0][0], d0, w2.x); FMA2(au[0][1], d0, w2.y);
      FMA2(au[1][0], d1, w2.x); FMA2(au[1][1], d1, w2.y);
    }
    float2 p01[2], p23[2];
    p01[0] = unpk(au[0][0]); p23[0] = unpk(au[0][1]);
    p01[1] = unpk(au[1][0]); p23[1] = unpk(au[1][1]);
    size_t o = (size_t)b * 1024 + j0;
    float2 u0 = {p01[0].x, p01[1].x};
    float2 u1 = {p01[0].y, p01[1].y};
    float2 u2 = {p23[0].x, p23[1].x};
    float2 u3 = {p23[0].y, p23[1].y};
    *(float2*)&g_U[o] = u0;
    *(float2*)&g_U[o + 256] = u1;
    *(float2*)&g_U[o + 512] = u2;
    *(float2*)&g_U[o + 768] = u3;
  }
}

// ---------------- launch ----------------
extern "C" void kernel_launch(void* const* d_in, const int* in_sizes, int n_in,
                              void* d_out, int out_size) {
  const float* x_u   = (const float*)d_in[0];
  const float* x_ctx = (const float*)d_in[1];
  const float* t_ctx = (const float*)d_in[2];
  const float* freq  = (const float*)d_in[3];
  const float* phase = (const float*)d_in[4];
  const float* Wq    = (const float*)d_in[5];
  const float* Wk    = (const float*)d_in[6];
  const float* Wv    = (const float*)d_in[7];
  const float* Wres  = (const float*)d_in[8];
  const float* bres  = (const float*)d_in[9];
  const float* W1    = (const float*)d_in[10];
  const float* b1    = (const float*)d_in[11];
  const float* W2    = (const float*)d_in[12];
  const float* b2    = (const float*)d_in[13];
  const float* g1    = (const float*)d_in[14];
  const float* be1   = (const float*)d_in[15];
  const float* g2    = (const float*)d_in[16];
  const float* be2   = (const float*)d_in[17];
  float* out = (float*)d_out;

  float *pWcat, *pPR, *pZ1, *pH1;
  cudaGetSymbolAddress((void**)&pWcat, g_Wcat);
  cudaGetSymbolAddress((void**)&pPR, g_PR);
  cudaGetSymbolAddress((void**)&pZ1, g_Z1);
  cudaGetSymbolAddress((void**)&pH1, g_H1);

  int smemEpi = (2 * 32 * 68 + 2 * 32 * 256) * 4;     // 82,944 B
  int smemHs = (2 * 16 * 4 * 68 + 2 * 16 * 256) * 4;  // 67,584 B
  cudaFuncSetAttribute(gemm_epi<0>, cudaFuncAttributeMaxDynamicSharedMemorySize, smemEpi);
  cudaFuncSetAttribute(gemm_epi<1>, cudaFuncAttributeMaxDynamicSharedMemorySize, smemEpi);
  cudaFuncSetAttribute(gemm_epi<2>, cudaFuncAttributeMaxDynamicSharedMemorySize, smemEpi);
  cudaFuncSetAttribute(gemm_hs, cudaFuncAttributeMaxDynamicSharedMemorySize, smemHs);

  mqk_kernel<<<dim3(4, 8), 256>>>(Wq, Wk);
  copy_wres_kernel<<<128, 256>>>(Wres);

  // K1: P|R = x_u @ Wcat
  gemm_epi<0><<<dim3(5, 256), 256, smemEpi>>>(x_u, pWcat, pPR, 128, 1280, 1280,
                                              nullptr, nullptr, 0, nullptr, nullptr);

  // K2: attention -> u
  attn_u_kernel<<<BB, 256>>>(x_ctx, t_ctx, freq, phase);

  // K3: z1 = LN(u_h @ Wv_h + R + bres)
  gemm_hs<<<dim3(1, 256), 256, smemHs>>>(Wv, pZ1, bres, pPR + 1024, 1280, g1, be1);

  // K4: h1 = relu(z1 @ W1 + b1)
  gemm_epi<1><<<dim3(1, 256), 256, smemEpi>>>(pZ1, W1, pH1, 256, 256, 256,
                                              b1, nullptr, 0, nullptr, nullptr);

  // K5: out = LN(h1 @ W2 + b2 + z1)
  gemm_epi<2><<<dim3(1, 256), 256, smemEpi>>>(pH1, W2, out, 256, 256, 256,
                                              b2, pZ1, 256, g2, be2);
}

// round 17
// speedup vs baseline: 1.0490x; 1.0007x over previous
#include <cuda_runtime.h>
#include <math.h>
#include <stdint.h>

#define BB 16384

__device__ __align__(16) float g_Wcat[128 * 1280];
__device__ __align__(16) float g_PR[(size_t)BB * 1280];
__device__ __align__(16) float g_U[(size_t)BB * 1024];
__device__ __align__(16) float g_Z1[(size_t)BB * 256];
__device__ __align__(16) float g_H1[(size_t)BB * 256];

__device__ __forceinline__ float wsum(float v) {
#pragma unroll
  for (int o = 16; o; o >>= 1) v += __shfl_xor_sync(0xffffffffu, v, o);
  return v;
}
__device__ __forceinline__ float wmax(float v) {
#pragma unroll
  for (int o = 16; o; o >>= 1) v = fmaxf(v, __shfl_xor_sync(0xffffffffu, v, o));
  return v;
}

#define FMA2(d, a, b) \
  asm("fma.rn.f32x2 %0, %1, %2, %0;" : "+l"(d) : "l"(a), "l"(b))
__device__ __forceinline__ unsigned long long dup2(float x) {
  unsigned long long r;
  asm("mov.b64 %0, {%1, %1};" : "=l"(r) : "f"(x));
  return r;
}
__device__ __forceinline__ float2 unpk(unsigned long long p) {
  float2 r;
  asm("mov.b64 {%0, %1}, %2;" : "=f"(r.x), "=f"(r.y) : "l"(p));
  return r;
}
__device__ __forceinline__ void cpa16(uint32_t s, const void* g) {
  asm volatile("cp.async.cg.shared.global [%0], [%1], 16;" :: "r"(s), "l"(g));
}
#define CP_COMMIT() asm volatile("cp.async.commit_group;" ::: "memory")
#define CP_WAIT0() asm volatile("cp.async.wait_group 0;" ::: "memory")

__device__ __forceinline__ int SW(int d) {
  return (d & ~31) | ((d & 31) ^ (((d >> 5) & 3) << 2));
}

__device__ __forceinline__ void fast_sincos(float z, float& s, float& c) {
  float t = rintf(z * 0.63661977236758134f);
  int qi = (int)t;
  float r = fmaf(t, -1.5703125f, z);
  r = fmaf(t, -4.83751296997070312e-4f, r);
  r = fmaf(t, -7.54978995489188e-8f, r);
  float r2 = r * r;
  float sp = fmaf(r2, -1.9515296e-4f, 8.3321608e-3f);
  sp = fmaf(r2, sp, -1.6666654611e-1f);
  float sinr = fmaf(r * r2, sp, r);
  float cp = fmaf(r2, -1.388731625493765e-3f, 4.166664568298827e-2f);
  cp = fmaf(r2, cp, -0.5f);
  float cosr = fmaf(r2, cp, 1.0f);
  int qq = qi & 3;
  float ss = (qq & 1) ? cosr : sinr;
  float cc = (qq & 1) ? sinr : cosr;
  s = (qq & 2) ? -ss : ss;
  c = ((qq + 1) & 2) ? -cc : cc;
}

// per-warp LN helper (proven)
__device__ __forceinline__ void ln_epilogue(
    float (*v)[4], int rbase, int colslab, int cb,
    float* redS, float* redQ,
    const float* gamma, const float* beta, float* C, int ldc, size_t m0) {
  int lane = threadIdx.x & 31;
#pragma unroll
  for (int r = 0; r < 16; r++) {
    float s = v[r][0] + v[r][1] + v[r][2] + v[r][3];
    float q = v[r][0] * v[r][0] + v[r][1] * v[r][1] +
              v[r][2] * v[r][2] + v[r][3] * v[r][3];
    s = wsum(s);
    q = wsum(q);
    if (lane == 0) {
      redS[colslab * 64 + rbase + r] = s;
      redQ[colslab * 64 + rbase + r] = q;
    }
  }
  __syncthreads();
  float4 gg = *(const float4*)&gamma[cb];
  float4 ee = *(const float4*)&beta[cb];
#pragma unroll
  for (int r = 0; r < 16; r++) {
    float s = redS[rbase + r] + redS[64 + rbase + r];
    float q = redQ[rbase + r] + redQ[64 + rbase + r];
    float mean = s * (1.f / 256.f);
    float var = fmaf(-mean, mean, q * (1.f / 256.f));
    float rstd = rsqrtf(var + 1e-5f);
    float4 o;
    o.x = (v[r][0] - mean) * rstd * gg.x + ee.x;
    o.y = (v[r][1] - mean) * rstd * gg.y + ee.y;
    o.z = (v[r][2] - mean) * rstd * gg.z + ee.z;
    o.w = (v[r][3] - mean) * rstd * gg.w + ee.w;
    *(float4*)&C[(m0 + rbase + r) * ldc + cb] = o;
  }
}

// ---------------- K0 ----------------
__global__ void __launch_bounds__(256) mqk_kernel(const float* __restrict__ Wq,
                                                  const float* __restrict__ Wk) {
  __shared__ float sWq[16 * 68];
  __shared__ float sWk[128 * 68];
  int h = blockIdx.x, is = blockIdx.y, tid = threadIdx.x;
  {
    int il = tid >> 4, d4 = tid & 15;
    *(float4*)&sWq[il * 68 + d4 * 4] =
        *(const float4*)&Wq[(size_t)(is * 16 + il) * 256 + h * 64 + d4 * 4];
  }
  for (int jc = 0; jc < 2; jc++) {
    __syncthreads();
#pragma unroll
    for (int it = 0; it < 8; it++) {
      int f = tid + it * 256, j = f >> 4, d4 = f & 15;
      *(float4*)&sWk[j * 68 + d4 * 4] =
          *(const float4*)&Wk[(size_t)(jc * 128 + j) * 256 + h * 64 + d4 * 4];
    }
    __syncthreads();
    int j = tid & 127, ih = tid >> 7;
#pragma unroll 1
    for (int il = ih * 8; il < ih * 8 + 8; il++) {
      float acc = 0.f;
#pragma unroll
      for (int d = 0; d < 64; d++) acc = fmaf(sWq[il * 68 + d], sWk[j * 68 + d], acc);
      g_Wcat[(size_t)(is * 16 + il) * 1280 + h * 256 + jc * 128 + j] = acc;
    }
  }
}

__global__ void copy_wres_kernel(const float* __restrict__ Wres) {
  g_Wcat[(size_t)blockIdx.x * 1280 + 1024 + threadIdx.x] =
      Wres[(size_t)blockIdx.x * 256 + threadIdx.x];
}

// ---------- SIMT GEMM, cp.async double-buffered, warp tile 16x128 ----------
// EPI: 0 store, 1 relu(x+bias), 2 LN(x+bias+resid) (gridDim.x==1)
template <int EPI>
__global__ void __launch_bounds__(256, 2) gemm_epi(
    const float* __restrict__ A, const float* __restrict__ W, float* __restrict__ C,
    int K, int ldw, int ldc, const float* __restrict__ bias,
    const float* __restrict__ resid, int ldres,
    const float* __restrict__ gamma, const float* __restrict__ beta) {
  extern __shared__ float smd[];
  float* sAT = smd;                 // [2][32*68]
  float* sB = smd + 2 * 32 * 68;    // [2][32*256]
  __shared__ float redS[128], redQ[128];
  int tid = threadIdx.x, lane = tid & 31, wid = tid >> 5;
  int rbase = (wid >> 1) * 16;
  int colslab = wid & 1;
  int cb = colslab * 128 + lane * 4;
  int m0 = blockIdx.y * 64, n0 = blockIdx.x * 256;
  unsigned long long acc[8][4];
#pragma unroll
  for (int i = 0; i < 8; i++)
#pragma unroll
    for (int j = 0; j < 4; j++) acc[i][j] = 0ull;

  uint32_t sBu = (uint32_t)__cvta_generic_to_shared(sB);
  int kt_n = K >> 5;
  float4 aR[2];
#pragma unroll
  for (int it = 0; it < 8; it++) {
    int f = tid + it * 256, kk = f >> 6, c4 = f & 63;
    cpa16(sBu + (kk * 256 + c4 * 4) * 4, &W[(size_t)kk * ldw + n0 + c4 * 4]);
  }
  CP_COMMIT();
#pragma unroll
  for (int it = 0; it < 2; it++) {
    int f = tid + it * 256, r = f >> 3, kq = f & 7;
    aR[it] = *(const float4*)&A[(size_t)(m0 + r) * K + kq * 4];
  }
#pragma unroll
  for (int it = 0; it < 2; it++) {
    int f = tid + it * 256, r = f >> 3, kq = f & 7;
    sAT[(kq * 4 + 0) * 68 + r] = aR[it].x;
    sAT[(kq * 4 + 1) * 68 + r] = aR[it].y;
    sAT[(kq * 4 + 2) * 68 + r] = aR[it].z;
    sAT[(kq * 4 + 3) * 68 + r] = aR[it].w;
  }
  CP_WAIT0();
  __syncthreads();

  for (int kt = 0; kt < kt_n; kt++) {
    int nb = (kt + 1) & 1;
    if (kt + 1 < kt_n) {
#pragma unroll
      for (int it = 0; it < 8; it++) {
        int f = tid + it * 256, kk = f >> 6, c4 = f & 63;
        cpa16(sBu + (nb * 32 * 256 + kk * 256 + c4 * 4) * 4,
              &W[(size_t)((kt + 1) * 32 + kk) * ldw + n0 + c4 * 4]);
      }
      CP_COMMIT();
#pragma unroll
      for (int it = 0; it < 2; it++) {
        int f = tid + it * 256, r = f >> 3, kq = f & 7;
        aR[it] = *(const float4*)&A[(size_t)(m0 + r) * K + (kt + 1) * 32 + kq * 4];
      }
    }
    const float* cA = sAT + (kt & 1) * 32 * 68;
    const float* cB = sB + (kt & 1) * 32 * 256;
#pragma unroll
    for (int kk = 0; kk < 32; kk++) {
      float4 bv = *(const float4*)&cB[kk * 256 + cb];
      unsigned long long bd0 = dup2(bv.x), bd1 = dup2(bv.y);
      unsigned long long bd2 = dup2(bv.z), bd3 = dup2(bv.w);
      const ulonglong2* ap = (const ulonglong2*)&cA[kk * 68 + rbase];
      ulonglong2 p0 = ap[0], p1 = ap[1], p2 = ap[2], p3 = ap[3];
      unsigned long long arr[8] = {p0.x, p0.y, p1.x, p1.y, p2.x, p2.y, p3.x, p3.y};
#pragma unroll
      for (int rp = 0; rp < 8; rp++) {
        FMA2(acc[rp][0], arr[rp], bd0);
        FMA2(acc[rp][1], arr[rp], bd1);
        FMA2(acc[rp][2], arr[rp], bd2);
        FMA2(acc[rp][3], arr[rp], bd3);
      }
    }
    if (kt + 1 < kt_n) {
      float* nA = sAT + nb * 32 * 68;
#pragma unroll
      for (int it = 0; it < 2; it++) {
        int f = tid + it * 256, r = f >> 3, kq = f & 7;
        nA[(kq * 4 + 0) * 68 + r] = aR[it].x;
        nA[(kq * 4 + 1) * 68 + r] = aR[it].y;
        nA[(kq * 4 + 2) * 68 + r] = aR[it].z;
        nA[(kq * 4 + 3) * 68 + r] = aR[it].w;
      }
      CP_WAIT0();
      __syncthreads();
    }
  }
  // ---- epilogue ----
  if (EPI == 2) {
    float v[16][4];
    float4 bv = *(const float4*)&bias[cb];
#pragma unroll
    for (int rp = 0; rp < 8; rp++) {
      float2 c0v = unpk(acc[rp][0]), c1v = unpk(acc[rp][1]);
      float2 c2v = unpk(acc[rp][2]), c3v = unpk(acc[rp][3]);
      float4 r0 = *(const float4*)&resid[(size_t)(m0 + rbase + 2 * rp) * ldres + cb];
      float4 r1 = *(const float4*)&resid[(size_t)(m0 + rbase + 2 * rp + 1) * ldres + cb];
      v[2 * rp][0] = c0v.x + bv.x + r0.x;
      v[2 * rp][1] = c1v.x + bv.y + r0.y;
      v[2 * rp][2] = c2v.x + bv.z + r0.z;
      v[2 * rp][3] = c3v.x + bv.w + r0.w;
      v[2 * rp + 1][0] = c0v.y + bv.x + r1.x;
      v[2 * rp + 1][1] = c1v.y + bv.y + r1.y;
      v[2 * rp + 1][2] = c2v.y + bv.z + r1.z;
      v[2 * rp + 1][3] = c3v.y + bv.w + r1.w;
    }
    ln_epilogue(v, rbase, colslab, cb, redS, redQ, gamma, beta, C, ldc, (size_t)m0);
    return;
  }
  float bb[4];
  if (EPI == 1) {
    float4 bv = *(const float4*)&bias[n0 + cb];
    bb[0] = bv.x; bb[1] = bv.y; bb[2] = bv.z; bb[3] = bv.w;
  }
#pragma unroll
  for (int rp = 0; rp < 8; rp++) {
    float2 c0v = unpk(acc[rp][0]), c1v = unpk(acc[rp][1]);
    float2 c2v = unpk(acc[rp][2]), c3v = unpk(acc[rp][3]);
    float4 o0 = {c0v.x, c1v.x, c2v.x, c3v.x};
    float4 o1 = {c0v.y, c1v.y, c2v.y, c3v.y};
    if (EPI == 1) {
      o0.x = fmaxf(o0.x + bb[0], 0.f); o0.y = fmaxf(o0.y + bb[1], 0.f);
      o0.z = fmaxf(o0.z + bb[2], 0.f); o0.w = fmaxf(o0.w + bb[3], 0.f);
      o1.x = fmaxf(o1.x + bb[0], 0.f); o1.y = fmaxf(o1.y + bb[1], 0.f);
      o1.z = fmaxf(o1.z + bb[2], 0.f); o1.w = fmaxf(o1.w + bb[3], 0.f);
    }
    *(float4*)&C[(size_t)(m0 + rbase + 2 * rp) * ldc + n0 + cb] = o0;
    *(float4*)&C[(size_t)(m0 + rbase + 2 * rp + 1) * ldc + n0 + cb] = o1;
  }
}

// ---------- K3: head-split GEMM + LN epilogue ----------
__global__ void __launch_bounds__(256, 2) gemm_hs(
    const float* __restrict__ Wv, float* __restrict__ C,
    const float* __restrict__ bias, const float* __restrict__ resid, int ldres,
    const float* __restrict__ gamma, const float* __restrict__ beta) {
  extern __shared__ float smd[];
  float* sAT = smd;                     // [2][16*4*68]
  float* sB = smd + 2 * 16 * 4 * 68;    // [2][16*256]
  __shared__ float redS[128], redQ[128];
  int tid = threadIdx.x, lane = tid & 31, wid = tid >> 5;
  int rbase = (wid >> 1) * 16;
  int colslab = wid & 1;
  int cb = colslab * 128 + lane * 4;
  int hl = colslab * 2 + (lane >> 4);
  int m0 = blockIdx.y * 64;
  unsigned long long acc[8][4];
#pragma unroll
  for (int i = 0; i < 8; i++)
#pragma unroll
    for (int j = 0; j < 4; j++) acc[i][j] = 0ull;

  uint32_t sBu = (uint32_t)__cvta_generic_to_shared(sB);
  float4 aR[4];
#pragma unroll
  for (int it = 0; it < 4; it++) {
    int f = tid + it * 256, kk = f >> 6, c4 = f & 63;
    cpa16(sBu + (kk * 256 + c4 * 4) * 4, &Wv[(size_t)kk * 256 + c4 * 4]);
  }
  CP_COMMIT();
#pragma unroll
  for (int it = 0; it < 4; it++) {
    int f = tid + it * 256, r = f >> 4, q = f & 15, h = q >> 2, kq = q & 3;
    aR[it] = *(const float4*)&g_U[(size_t)(m0 + r) * 1024 + h * 256 + kq * 4];
  }
#pragma unroll
  for (int it = 0; it < 4; it++) {
    int f = tid + it * 256, r = f >> 4, q = f & 15, h = q >> 2, kq = q & 3;
    sAT[((kq * 4 + 0) * 4 + h) * 68 + r] = aR[it].x;
    sAT[((kq * 4 + 1) * 4 + h) * 68 + r] = aR[it].y;
    sAT[((kq * 4 + 2) * 4 + h) * 68 + r] = aR[it].z;
    sAT[((kq * 4 + 3) * 4 + h) * 68 + r] = aR[it].w;
  }
  CP_WAIT0();
  __syncthreads();

  for (int kt = 0; kt < 16; kt++) {
    int nb = (kt + 1) & 1;
    if (kt + 1 < 16) {
#pragma unroll
      for (int it = 0; it < 4; it++) {
        int f = tid + it * 256, kk = f >> 6, c4 = f & 63;
        cpa16(sBu + (nb * 16 * 256 + kk * 256 + c4 * 4) * 4,
              &Wv[(size_t)((kt + 1) * 16 + kk) * 256 + c4 * 4]);
      }
      CP_COMMIT();
#pragma unroll
      for (int it = 0; it < 4; it++) {
        int f = tid + it * 256, r = f >> 4, q = f & 15, h = q >> 2, kq = q & 3;
        aR[it] = *(const float4*)&g_U[(size_t)(m0 + r) * 1024 + h * 256 +
                                      (kt + 1) * 16 + kq * 4];
      }
    }
    const float* cA = sAT + (kt & 1) * 16 * 4 * 68;
    const float* cB = sB + (kt & 1) * 16 * 256;
#pragma unroll
    for (int kk = 0; kk < 16; kk++) {
      float4 bv = *(const float4*)&cB[kk * 256 + cb];
      unsigned long long bd0 = dup2(bv.x), bd1 = dup2(bv.y);
      unsigned long long bd2 = dup2(bv.z), bd3 = dup2(bv.w);
      const ulonglong2* ap = (const ulonglong2*)&cA[(kk * 4 + hl) * 68 + rbase];
      ulonglong2 p0 = ap[0], p1 = ap[1], p2 = ap[2], p3 = ap[3];
      unsigned long long arr[8] = {p0.x, p0.y, p1.x, p1.y, p2.x, p2.y, p3.x, p3.y};
#pragma unroll
      for (int rp = 0; rp < 8; rp++) {
        FMA2(acc[rp][0], arr[rp], bd0);
        FMA2(acc[rp][1], arr[rp], bd1);
        FMA2(acc[rp][2], arr[rp], bd2);
        FMA2(acc[rp][3], arr[rp], bd3);
      }
    }
    if (kt + 1 < 16) {
      float* nA = sAT + nb * 16 * 4 * 68;
#pragma unroll
      for (int it = 0; it < 4; it++) {
        int f = tid + it * 256, r = f >> 4, q = f & 15, h = q >> 2, kq = q & 3;
        nA[((kq * 4 + 0) * 4 + h) * 68 + r] = aR[it].x;
        nA[((kq * 4 + 1) * 4 + h) * 68 + r] = aR[it].y;
        nA[((kq * 4 + 2) * 4 + h) * 68 + r] = aR[it].z;
        nA[((kq * 4 + 3) * 4 + h) * 68 + r] = aR[it].w;
      }
      CP_WAIT0();
      __syncthreads();
    }
  }
  float v[16][4];
  float4 bv = *(const float4*)&bias[cb];
#pragma unroll
  for (int rp = 0; rp < 8; rp++) {
    float2 c0v = unpk(acc[rp][0]), c1v = unpk(acc[rp][1]);
    float2 c2v = unpk(acc[rp][2]), c3v = unpk(acc[rp][3]);
    float4 r0 = *(const float4*)&resid[(size_t)(m0 + rbase + 2 * rp) * ldres + cb];
    float4 r1 = *(const float4*)&resid[(size_t)(m0 + rbase + 2 * rp + 1) * ldres + cb];
    v[2 * rp][0] = c0v.x + bv.x + r0.x;
    v[2 * rp][1] = c1v.x + bv.y + r0.y;
    v[2 * rp][2] = c2v.x + bv.z + r0.z;
    v[2 * rp][3] = c3v.x + bv.w + r0.w;
    v[2 * rp + 1][0] = c0v.y + bv.x + r1.x;
    v[2 * rp + 1][1] = c1v.y + bv.y + r1.y;
    v[2 * rp + 1][2] = c2v.y + bv.z + r1.z;
    v[2 * rp + 1][3] = c3v.y + bv.w + r1.w;
  }
  ln_epilogue(v, rbase, colslab, cb, redS, redQ, gamma, beta, C, 256, (size_t)m0);
}

// ---------------- K2: attention (R11-proven) ----------------
__global__ void __launch_bounds__(256) attn_u_kernel(
    const float* __restrict__ x_ctx, const float* __restrict__ t_ctx,
    const float* __restrict__ freq, const float* __restrict__ phase) {
  __shared__ float kv[32 * 260];
  __shared__ float p2[4 * 8 * 36];
  __shared__ float slog[128];
  __shared__ __align__(16) float sw[128];
  __shared__ float sfr[64], sph[64];
  int b = blockIdx.x, tid = threadIdx.x;
  int l = tid >> 3, sub = tid & 7;

  if (tid < 64) {
    sfr[tid] = freq[tid];
    sph[tid] = phase[tid];
  }
  {
    int h = tid >> 6, r = tid & 63, s2 = r >> 3, c = r & 7;
    int idx4;
    if (c < 4) idx4 = h * 64 + s2 * 4 + c;
    else if (c < 6) idx4 = h * 64 + 32 + s2 * 2 + (c - 4);
    else idx4 = h * 64 + 48 + s2 * 2 + (c - 6);
    float4 v = *(const float4*)&g_PR[(size_t)b * 1280 + (size_t)idx4 * 4];
    *(float4*)&p2[(h * 8 + s2) * 36 + c * 4] = v;
  }
  __syncthreads();

  float acc[4] = {0.f, 0.f, 0.f, 0.f};
  const float* xsrc = x_ctx + ((size_t)b * 32 + l) * 128 + sub * 16;
  float* kvrow = kv + l * 260;

#pragma unroll
  for (int c = 0; c < 4; c++) {
    float4 v = *(const float4*)&xsrc[c * 4];
    *(float4*)&kvrow[SW(sub * 16 + c * 4)] = v;
#pragma unroll
    for (int h = 0; h < 4; h++) {
      float4 p = *(const float4*)&p2[(h * 8 + sub) * 36 + c * 4];
      acc[h] = fmaf(v.x, p.x, acc[h]);
      acc[h] = fmaf(v.y, p.y, acc[h]);
      acc[h] = fmaf(v.z, p.z, acc[h]);
      acc[h] = fmaf(v.w, p.w, acc[h]);
    }
  }
  {
    float t = t_ctx[(size_t)b * 32 + l];
    float lt = log1pf(fmaxf(t, 0.f));
#pragma unroll
    for (int g = 0; g < 2; g++) {
      float4 sv, cv;
      float ss, cc;
      int k0 = sub * 8 + g * 4;
      float z0 = fmaf(lt, sfr[k0 + 0], sph[k0 + 0]);
      float z1 = fmaf(lt, sfr[k0 + 1], sph[k0 + 1]);
      float z2 = fmaf(lt, sfr[k0 + 2], sph[k0 + 2]);
      float z3 = fmaf(lt, sfr[k0 + 3], sph[k0 + 3]);
      fast_sincos(z0, ss, cc); sv.x = ss; cv.x = cc;
      fast_sincos(z1, ss, cc); sv.y = ss; cv.y = cc;
      fast_sincos(z2, ss, cc); sv.z = ss; cv.z = cc;
      fast_sincos(z3, ss, cc); sv.w = ss; cv.w = cc;
      *(float4*)&kvrow[SW(128 + sub * 8 + g * 4)] = sv;
      *(float4*)&kvrow[SW(192 + sub * 8 + g * 4)] = cv;
#pragma unroll
      for (int h = 0; h < 4; h++) {
        float4 ps = *(const float4*)&p2[(h * 8 + sub) * 36 + (4 + g) * 4];
        float4 pc = *(const float4*)&p2[(h * 8 + sub) * 36 + (6 + g) * 4];
        acc[h] = fmaf(sv.x, ps.x, acc[h]);
        acc[h] = fmaf(sv.y, ps.y, acc[h]);
        acc[h] = fmaf(sv.z, ps.z, acc[h]);
        acc[h] = fmaf(sv.w, ps.w, acc[h]);
        acc[h] = fmaf(cv.x, pc.x, acc[h]);
        acc[h] = fmaf(cv.y, pc.y, acc[h]);
        acc[h] = fmaf(cv.z, pc.z, acc[h]);
        acc[h] = fmaf(cv.w, pc.w, acc[h]);
      }
    }
  }
#pragma unroll
  for (int h = 0; h < 4; h++) {
#pragma unroll
    for (int o = 4; o; o >>= 1) acc[h] += __shfl_xor_sync(0xffffffffu, acc[h], o);
  }
  if (sub < 4) slog[sub * 32 + l] = acc[sub] * 0.125f;
  __syncthreads();
  if (tid < 128) {
    int h = tid >> 5, ll = tid & 31;
    float v = slog[tid];
    float m = wmax(v);
    float e = __expf(v - m);
    float s = wsum(e);
    sw[ll * 4 + h] = e / s;
  }
  __syncthreads();
  // u-phase: 64 threads, thread owns dims j0..j0+3 (float4), all 4 heads
  if (tid < 64) {
    int j0 = tid * 4;
    int sj = SW(j0);
    unsigned long long au[4][2];
#pragma unroll
    for (int d = 0; d < 4; d++) { au[d][0] = 0ull; au[d][1] = 0ull; }
#pragma unroll
    for (int ll = 0; ll < 32; ll++) {
      float4 kq = *(const float4*)&kv[ll * 260 + sj];
      ulonglong2 w2 = *(const ulonglong2*)&sw[ll * 4];
      unsigned long long d0 = dup2(kq.x), d1 = dup2(kq.y);
      unsigned long long d2 = dup2(kq.z), d3 = dup2(kq.w);
      FMA2(au[0][0], d0, w2.x); FMA2(au[0][1], d0, w2.y);
      FMA2(au[1][0], d1, w2.x); FMA2(au[1][1], d1, w2.y);
      FMA2(au[2][0], d2, w2.x); FMA2(au[2][1], d2, w2.y);
      FMA2(au[3][0], d3, w2.x); FMA2(au[3][1], d3, w2.y);
    }
    float2 p01[4], p23[4];
#pragma unroll
    for (int d = 0; d < 4; d++) {
      p01[d] = unpk(au[d][0]);
      p23[d] = unpk(au[d][1]);
    }
    size_t o = (size_t)b * 1024 + j0;
    float4 u0 = {p01[0].x, p01[1].x, p01[2].x, p01[3].x};
    float4 u1 = {p01[0].y, p01[1].y, p01[2].y, p01[3].y};
    float4 u2 = {p23[0].x, p23[1].x, p23[2].x, p23[3].x};
    float4 u3 = {p23[0].y, p23[1].y, p23[2].y, p23[3].y};
    *(float4*)&g_U[o] = u0;
    *(float4*)&g_U[o + 256] = u1;
    *(float4*)&g_U[o + 512] = u2;
    *(float4*)&g_U[o + 768] = u3;
  }
}

// ---------------- launch ----------------
extern "C" void kernel_launch(void* const* d_in, const int* in_sizes, int n_in,
                              void* d_out, int out_size) {
  const float* x_u   = (const float*)d_in[0];
  const float* x_ctx = (const float*)d_in[1];
  const float* t_ctx = (const float*)d_in[2];
  const float* freq  = (const float*)d_in[3];
  const float* phase = (const float*)d_in[4];
  const float* Wq    = (const float*)d_in[5];
  const float* Wk    = (const float*)d_in[6];
  const float* Wv    = (const float*)d_in[7];
  const float* Wres  = (const float*)d_in[8];
  const float* bres  = (const float*)d_in[9];
  const float* W1    = (const float*)d_in[10];
  const float* b1    = (const float*)d_in[11];
  const float* W2    = (const float*)d_in[12];
  const float* b2    = (const float*)d_in[13];
  const float* g1    = (const float*)d_in[14];
  const float* be1   = (const float*)d_in[15];
  const float* g2    = (const float*)d_in[16];
  const float* be2   = (const float*)d_in[17];
  float* out = (float*)d_out;

  float *pWcat, *pPR, *pZ1, *pH1;
  cudaGetSymbolAddress((void**)&pWcat, g_Wcat);
  cudaGetSymbolAddress((void**)&pPR, g_PR);
  cudaGetSymbolAddress((void**)&pZ1, g_Z1);
  cudaGetSymbolAddress((void**)&pH1, g_H1);

  int smemEpi = (2 * 32 * 68 + 2 * 32 * 256) * 4;     // 82,944 B
  int smemHs = (2 * 16 * 4 * 68 + 2 * 16 * 256) * 4;  // 67,584 B
  cudaFuncSetAttribute(gemm_epi<0>, cudaFuncAttributeMaxDynamicSharedMemorySize, smemEpi);
  cudaFuncSetAttribute(gemm_epi<1>, cudaFuncAttributeMaxDynamicSharedMemorySize, smemEpi);
  cudaFuncSetAttribute(gemm_epi<2>, cudaFuncAttributeMaxDynamicSharedMemorySize, smemEpi);
  cudaFuncSetAttribute(gemm_hs, cudaFuncAttributeMaxDynamicSharedMemorySize, smemHs);

  mqk_kernel<<<dim3(4, 8), 256>>>(Wq, Wk);
  copy_wres_kernel<<<128, 256>>>(Wres);

  // K1: P|R = x_u @ Wcat
  gemm_epi<0><<<dim3(5, 256), 256, smemEpi>>>(x_u, pWcat, pPR, 128, 1280, 1280,
                                              nullptr, nullptr, 0, nullptr, nullptr);

  // K2: attention -> u
  attn_u_kernel<<<BB, 256>>>(x_ctx, t_ctx, freq, phase);

  // K3: z1 = LN(u_h @ Wv_h + R + bres)
  gemm_hs<<<dim3(1, 256), 256, smemHs>>>(Wv, pZ1, bres, pPR + 1024, 1280, g1, be1);

  // K4: h1 = relu(z1 @ W1 + b1)
  gemm_epi<1><<<dim3(1, 256), 256, smemEpi>>>(pZ1, W1, pH1, 256, 256, 256,
                                              b1, nullptr, 0, nullptr, nullptr);

  // K5: out = LN(h1 @ W2 + b2 + z1)
  gemm_epi<2><<<dim3(1, 256), 256, smemEpi>>>(pH1, W2, out, 256, 256, 256,
                                              b2, pZ1, 256, g2, be2);
}